// round 4
// baseline (speedup 1.0000x reference)
#include <cuda_runtime.h>
#include <stdint.h>

#define NUM_CLASSES 100000
#define EMBED_DIM   512
#define BATCH       16384
// diff = (1 - 0.95) * (centers - features)
#define ONE_MINUS_ALPHA 0.05f

// ---- device scratch (no allocations allowed) ----
__device__ double g_loss_acc;
__device__ int    g_odd_nonzero;          // 1 if any odd int32 word of label buf != 0
__device__ int    g_labels[BATCH];        // decoded labels

__global__ void init_kernel() {
    g_loss_acc = 0.0;
    g_odd_nonzero = 0;
}

// Detect label dtype. If labels are int64 (values < 2^31), every odd int32
// word is 0. If int32, odd words are real labels -> some nonzero.
// All reads stay within the first BATCH int32 words (valid for both dtypes).
__global__ void detect_labels_kernel(const int* __restrict__ lab32) {
    int any = 0;
    for (int i = blockIdx.x * blockDim.x + threadIdx.x; i < BATCH / 2;
         i += gridDim.x * blockDim.x) {
        if (lab32[2 * i + 1] != 0) any = 1;
    }
    if (any) atomicOr(&g_odd_nonzero, 1);
}

// Widen/decode labels into g_labels based on the detected dtype.
__global__ void convert_labels_kernel(const void* __restrict__ labels_raw) {
    int is32 = g_odd_nonzero;   // odd words nonzero -> buffer is int32
    for (int i = blockIdx.x * blockDim.x + threadIdx.x; i < BATCH;
         i += gridDim.x * blockDim.x) {
        int v;
        if (is32) {
            v = ((const int*)labels_raw)[i];
        } else {
            v = (int)((const long long*)labels_raw)[i];
        }
        // clamp defensively: never generate an OOB gather/scatter
        if (v < 0) v = 0;
        if (v >= NUM_CLASSES) v = NUM_CLASSES - 1;
        g_labels[i] = v;
    }
}

// Copy center_var -> out_centers. dst may be only 4B-aligned (loss-first
// layout), so vector loads + scalar stores.
__global__ void copy_centers_kernel(const float4* __restrict__ src,
                                    float* __restrict__ dst) {
    const long long n4 = (long long)NUM_CLASSES * EMBED_DIM / 4;
    long long stride = (long long)gridDim.x * blockDim.x;
    for (long long i = (long long)blockIdx.x * blockDim.x + threadIdx.x;
         i < n4; i += stride) {
        float4 v = src[i];
        long long j = i * 4;
        dst[j + 0] = v.x;
        dst[j + 1] = v.y;
        dst[j + 2] = v.z;
        dst[j + 3] = v.w;
    }
}

// One block of 128 threads per sample; each thread owns one float4 of 512 dims.
// Gathers the PRE-update center, atomically applies -0.05*(c-f) to the output
// row (duplicate labels accumulate), and block-reduces (f-c)^2 into g_loss_acc.
__global__ void scatter_loss_kernel(const float* __restrict__ features,
                                    const float* __restrict__ center_var,
                                    float*       __restrict__ out_centers) {
    const int b = blockIdx.x;
    const int t = threadIdx.x;  // 0..127

    const long long lab = (long long)g_labels[b];

    const float4* f4 = (const float4*)(features + (long long)b * EMBED_DIM);
    const float4* c4 = (const float4*)(center_var + lab * EMBED_DIM);

    float4 f = f4[t];
    float4 c = c4[t];

    float dx = c.x - f.x;
    float dy = c.y - f.y;
    float dz = c.z - f.z;
    float dw = c.w - f.w;

    float sq = dx * dx + dy * dy + dz * dz + dw * dw;

    float* obase = out_centers + lab * EMBED_DIM + (long long)t * 4;
    atomicAdd(obase + 0, -ONE_MINUS_ALPHA * dx);
    atomicAdd(obase + 1, -ONE_MINUS_ALPHA * dy);
    atomicAdd(obase + 2, -ONE_MINUS_ALPHA * dz);
    atomicAdd(obase + 3, -ONE_MINUS_ALPHA * dw);

    // Block reduce sq (128 threads = 4 warps)
    #pragma unroll
    for (int off = 16; off > 0; off >>= 1)
        sq += __shfl_down_sync(0xFFFFFFFFu, sq, off);

    __shared__ float warp_sums[4];
    if ((t & 31) == 0) warp_sums[t >> 5] = sq;
    __syncthreads();
    if (t == 0) {
        float s = warp_sums[0] + warp_sums[1] + warp_sums[2] + warp_sums[3];
        atomicAdd(&g_loss_acc, (double)s);
    }
}

__global__ void finalize_loss_kernel(float* __restrict__ out_loss) {
    *out_loss = (float)(g_loss_acc / ((double)BATCH * (double)EMBED_DIM));
}

extern "C" void kernel_launch(void* const* d_in, const int* in_sizes, int n_in,
                              void* d_out, int out_size) {
    // Identify inputs by element count (robust to ordering surprises).
    const float* features   = nullptr;
    const void*  labels_raw = nullptr;
    const float* center_var = nullptr;
    for (int i = 0; i < n_in; i++) {
        if (in_sizes[i] == BATCH)                       labels_raw = d_in[i];
        else if (in_sizes[i] == BATCH * EMBED_DIM)      features   = (const float*)d_in[i];
        else if (in_sizes[i] == NUM_CLASSES * EMBED_DIM) center_var = (const float*)d_in[i];
    }
    // Fallback to positional if sizes were ambiguous.
    if (!features)   features   = (const float*)d_in[0];
    if (!labels_raw) labels_raw = d_in[1];
    if (!center_var) center_var = (const float*)d_in[2];

    float* out = (float*)d_out;
    // Expected: out[0]=loss, out[1..]=new_centers. Compute offset defensively.
    long long centers_off = (long long)out_size - (long long)NUM_CLASSES * EMBED_DIM;
    if (centers_off < 0) centers_off = 0;
    float* out_loss    = out;
    float* out_centers = out + centers_off;

    init_kernel<<<1, 1>>>();
    detect_labels_kernel<<<16, 256>>>((const int*)labels_raw);
    convert_labels_kernel<<<64, 256>>>(labels_raw);

    copy_centers_kernel<<<1184, 256>>>((const float4*)center_var, out_centers);

    scatter_loss_kernel<<<BATCH, 128>>>(features, center_var, out_centers);

    finalize_loss_kernel<<<1, 1>>>(out_loss);
}

// round 8
// speedup vs baseline: 2.1660x; 2.1660x over previous
#include <cuda_runtime.h>
#include <stdint.h>

#define NUM_CLASSES 100000
#define EMBED_DIM   512
#define BATCH       16384
#define ONE_MINUS_ALPHA 0.05f

// ---- device scratch (static; no allocations) ----
__device__ double g_loss_acc;
__device__ int    g_odd_nonzero;            // label dtype probe
__device__ int    g_head[NUM_CLASSES];      // per-class list head (-1 = empty)
__device__ int    g_next[BATCH];            // per-sample next link

// Init: head = -1 everywhere, zero loss + dtype flag.
__global__ void init_kernel() {
    int stride = gridDim.x * blockDim.x;
    for (int i = blockIdx.x * blockDim.x + threadIdx.x; i < NUM_CLASSES; i += stride)
        g_head[i] = -1;
    if (blockIdx.x == 0 && threadIdx.x == 0) {
        g_loss_acc = 0.0;
        g_odd_nonzero = 0;
    }
}

// Label dtype probe: int64 labels (< 2^31) have zero odd int32 words;
// int32 labels have real (mostly nonzero) values there.
__global__ void detect_labels_kernel(const int* __restrict__ lab32) {
    int any = 0;
    for (int i = blockIdx.x * blockDim.x + threadIdx.x; i < BATCH / 2;
         i += gridDim.x * blockDim.x) {
        if (lab32[2 * i + 1] != 0) any = 1;
    }
    if (any) atomicOr(&g_odd_nonzero, 1);
}

// Decode labels and build per-class linked lists via atomicExch.
__global__ void build_lists_kernel(const void* __restrict__ labels_raw) {
    int is32 = g_odd_nonzero;
    for (int i = blockIdx.x * blockDim.x + threadIdx.x; i < BATCH;
         i += gridDim.x * blockDim.x) {
        int v = is32 ? ((const int*)labels_raw)[i]
                     : (int)((const long long*)labels_raw)[i];
        if (v < 0) v = 0;
        if (v >= NUM_CLASSES) v = NUM_CLASSES - 1;
        g_next[i] = atomicExch(&g_head[v], i);
    }
}

// Fused pass: one 128-thread block per class row.
// Each thread owns one float4 (4 of 512 dims). Walk this class's sample
// list, accumulate delta = sum(c - f) and sq = sum((f-c)^2), then write
// new = c - 0.05*delta exactly once. Loss atomic only for touched rows.
__global__ void __launch_bounds__(128)
row_kernel(const float* __restrict__ features,
           const float* __restrict__ center_var,
           float*       __restrict__ out_centers) {
    const int row = blockIdx.x;
    const int t   = threadIdx.x;  // 0..127

    const float4* c4 = (const float4*)(center_var + (long long)row * EMBED_DIM);
    float4 c = __ldcs(c4 + t);   // streamed: no reuse of source centers

    float dx = 0.f, dy = 0.f, dz = 0.f, dw = 0.f;   // sum(c - f)
    float sq = 0.f;
    int   n  = 0;

    // All threads walk the (short) list redundantly; the index loads are
    // warp-uniform broadcasts, the feature loads are the real traffic.
    for (int s = g_head[row]; s >= 0; s = g_next[s]) {
        const float4* f4 = (const float4*)(features + (long long)s * EMBED_DIM);
        float4 f = __ldcs(f4 + t);
        float ex = c.x - f.x, ey = c.y - f.y, ez = c.z - f.z, ew = c.w - f.w;
        dx += ex; dy += ey; dz += ez; dw += ew;
        sq += ex * ex + ey * ey + ez * ez + ew * ew;
        n++;
    }

    // Output row: dest is only 4B-aligned (loss at out[0]) -> scalar stores.
    float* o = out_centers + (long long)row * EMBED_DIM + t * 4;
    __stcs(o + 0, c.x - ONE_MINUS_ALPHA * dx);
    __stcs(o + 1, c.y - ONE_MINUS_ALPHA * dy);
    __stcs(o + 2, c.z - ONE_MINUS_ALPHA * dz);
    __stcs(o + 3, c.w - ONE_MINUS_ALPHA * dw);

    if (n > 0) {
        // Block reduce sq (4 warps)
        #pragma unroll
        for (int off = 16; off > 0; off >>= 1)
            sq += __shfl_down_sync(0xFFFFFFFFu, sq, off);
        __shared__ float warp_sums[4];
        if ((t & 31) == 0) warp_sums[t >> 5] = sq;
        __syncthreads();
        if (t == 0) {
            float s = warp_sums[0] + warp_sums[1] + warp_sums[2] + warp_sums[3];
            atomicAdd(&g_loss_acc, (double)s);
        }
    }
}

__global__ void finalize_loss_kernel(float* __restrict__ out_loss) {
    *out_loss = (float)(g_loss_acc / ((double)BATCH * (double)EMBED_DIM));
}

extern "C" void kernel_launch(void* const* d_in, const int* in_sizes, int n_in,
                              void* d_out, int out_size) {
    const float* features   = nullptr;
    const void*  labels_raw = nullptr;
    const float* center_var = nullptr;
    for (int i = 0; i < n_in; i++) {
        if (in_sizes[i] == BATCH)                        labels_raw = d_in[i];
        else if (in_sizes[i] == BATCH * EMBED_DIM)       features   = (const float*)d_in[i];
        else if (in_sizes[i] == NUM_CLASSES * EMBED_DIM) center_var = (const float*)d_in[i];
    }
    if (!features)   features   = (const float*)d_in[0];
    if (!labels_raw) labels_raw = d_in[1];
    if (!center_var) center_var = (const float*)d_in[2];

    float* out = (float*)d_out;
    long long centers_off = (long long)out_size - (long long)NUM_CLASSES * EMBED_DIM;
    if (centers_off < 0) centers_off = 0;
    float* out_loss    = out;
    float* out_centers = out + centers_off;

    init_kernel<<<256, 256>>>();
    detect_labels_kernel<<<16, 256>>>((const int*)labels_raw);
    build_lists_kernel<<<64, 256>>>(labels_raw);
    row_kernel<<<NUM_CLASSES, 128>>>(features, center_var, out_centers);
    finalize_loss_kernel<<<1, 1>>>(out_loss);
}

// round 10
// speedup vs baseline: 2.2734x; 1.0496x over previous
#include <cuda_runtime.h>
#include <stdint.h>

#define NUM_CLASSES 100000
#define EMBED_DIM   512
#define BATCH       16384
#define ONE_MINUS_ALPHA 0.05f

#define ROWS_PER_BLOCK 4
#define THREADS_RK     256   // 64 threads per row

// ---- device scratch (static; no allocations) ----
// Zero-initialized at load; finalize re-zeros loss/flag each call so graph
// replays are deterministic.
__device__ double g_loss_acc;               // = 0.0 initially
__device__ int    g_odd_nonzero;            // label dtype probe, = 0 initially
__device__ int    g_head[NUM_CLASSES];      // per-class list head (-1 = empty)
__device__ int    g_next[BATCH];            // per-sample next link

// Fused: reset heads to -1 AND probe label dtype.
// int64 labels (< 2^31) have all-zero odd int32 words; int32 labels have
// real label values there (essentially surely nonzero among 8192 words).
__global__ void init_detect_kernel(const int* __restrict__ lab32) {
    const int stride = gridDim.x * blockDim.x;
    const int tid = blockIdx.x * blockDim.x + threadIdx.x;
    for (int i = tid; i < NUM_CLASSES; i += stride)
        g_head[i] = -1;
    int any = 0;
    for (int i = tid; i < BATCH / 2; i += stride)
        if (lab32[2 * i + 1] != 0) any = 1;
    if (any) atomicOr(&g_odd_nonzero, 1);
}

// Decode labels per detected dtype; build per-class linked lists.
__global__ void build_lists_kernel(const void* __restrict__ labels_raw) {
    const int is32 = g_odd_nonzero;
    for (int i = blockIdx.x * blockDim.x + threadIdx.x; i < BATCH;
         i += gridDim.x * blockDim.x) {
        int v = is32 ? ((const int*)labels_raw)[i]
                     : (int)((const long long*)labels_raw)[i];
        if (v < 0) v = 0;
        if (v >= NUM_CLASSES) v = NUM_CLASSES - 1;
        g_next[i] = atomicExch(&g_head[v], i);
    }
}

// Fused pass: 256 threads per block, 4 rows per block, 64 threads per row.
// Each thread owns TWO stride-separated float4s of its row (8 floats) for
// 2x memory-level parallelism. Walk the class's sample list, accumulate
// sum(c-f) and sum((f-c)^2), write new = c - 0.05*sum(c-f) exactly once.
__global__ void __launch_bounds__(THREADS_RK)
row_kernel(const float* __restrict__ features,
           const float* __restrict__ center_var,
           float*       __restrict__ out_centers) {
    const int t    = threadIdx.x;
    const int sub  = t >> 6;        // 0..3: row within block
    const int lane = t & 63;        // 0..63: quarter-row lane
    const long long row = (long long)blockIdx.x * ROWS_PER_BLOCK + sub;

    const float4* c4 = (const float4*)(center_var + row * EMBED_DIM);
    // Two fully-coalesced halves: [lane] covers floats [0,256), [lane+64] covers [256,512)
    float4 c0 = __ldcs(c4 + lane);
    float4 c1 = __ldcs(c4 + lane + 64);

    float4 d0 = make_float4(0.f, 0.f, 0.f, 0.f);   // sum(c - f), first half
    float4 d1 = make_float4(0.f, 0.f, 0.f, 0.f);   // sum(c - f), second half
    float sq = 0.f;
    int   n  = 0;

    for (int s = g_head[row]; s >= 0; s = g_next[s]) {
        const float4* f4 = (const float4*)(features + (long long)s * EMBED_DIM);
        float4 f0 = __ldcs(f4 + lane);
        float4 f1 = __ldcs(f4 + lane + 64);
        float e;
        e = c0.x - f0.x; d0.x += e; sq += e * e;
        e = c0.y - f0.y; d0.y += e; sq += e * e;
        e = c0.z - f0.z; d0.z += e; sq += e * e;
        e = c0.w - f0.w; d0.w += e; sq += e * e;
        e = c1.x - f1.x; d1.x += e; sq += e * e;
        e = c1.y - f1.y; d1.y += e; sq += e * e;
        e = c1.z - f1.z; d1.z += e; sq += e * e;
        e = c1.w - f1.w; d1.w += e; sq += e * e;
        n++;
    }

    // Output rows are +1 float misaligned (loss at out[0]) -> scalar stores.
    float* o0 = out_centers + row * EMBED_DIM + lane * 4;
    float* o1 = o0 + 256;
    __stcs(o0 + 0, c0.x - ONE_MINUS_ALPHA * d0.x);
    __stcs(o0 + 1, c0.y - ONE_MINUS_ALPHA * d0.y);
    __stcs(o0 + 2, c0.z - ONE_MINUS_ALPHA * d0.z);
    __stcs(o0 + 3, c0.w - ONE_MINUS_ALPHA * d0.w);
    __stcs(o1 + 0, c1.x - ONE_MINUS_ALPHA * d1.x);
    __stcs(o1 + 1, c1.y - ONE_MINUS_ALPHA * d1.y);
    __stcs(o1 + 2, c1.z - ONE_MINUS_ALPHA * d1.z);
    __stcs(o1 + 3, c1.w - ONE_MINUS_ALPHA * d1.w);

    // Block-wide loss reduce (8 warps), one atomic per block with samples.
    #pragma unroll
    for (int off = 16; off > 0; off >>= 1)
        sq += __shfl_down_sync(0xFFFFFFFFu, sq, off);
    __shared__ float ws[THREADS_RK / 32];
    if ((t & 31) == 0) ws[t >> 5] = sq;
    const int any = __syncthreads_or(n > 0);   // barrier also publishes ws
    if (t == 0 && any) {
        float s = 0.f;
        #pragma unroll
        for (int w = 0; w < THREADS_RK / 32; w++) s += ws[w];
        atomicAdd(&g_loss_acc, (double)s);
    }
}

// Write loss, then reset per-call scratch so the next graph replay starts clean.
__global__ void finalize_loss_kernel(float* __restrict__ out_loss) {
    *out_loss = (float)(g_loss_acc / ((double)BATCH * (double)EMBED_DIM));
    g_loss_acc = 0.0;
    g_odd_nonzero = 0;
}

extern "C" void kernel_launch(void* const* d_in, const int* in_sizes, int n_in,
                              void* d_out, int out_size) {
    const float* features   = nullptr;
    const void*  labels_raw = nullptr;
    const float* center_var = nullptr;
    for (int i = 0; i < n_in; i++) {
        if (in_sizes[i] == BATCH)                        labels_raw = d_in[i];
        else if (in_sizes[i] == BATCH * EMBED_DIM)       features   = (const float*)d_in[i];
        else if (in_sizes[i] == NUM_CLASSES * EMBED_DIM) center_var = (const float*)d_in[i];
    }
    if (!features)   features   = (const float*)d_in[0];
    if (!labels_raw) labels_raw = d_in[1];
    if (!center_var) center_var = (const float*)d_in[2];

    float* out = (float*)d_out;
    long long centers_off = (long long)out_size - (long long)NUM_CLASSES * EMBED_DIM;
    if (centers_off < 0) centers_off = 0;
    float* out_loss    = out;
    float* out_centers = out + centers_off;

    init_detect_kernel<<<200, 256>>>((const int*)labels_raw);
    build_lists_kernel<<<64, 256>>>(labels_raw);
    row_kernel<<<NUM_CLASSES / ROWS_PER_BLOCK, THREADS_RK>>>(features, center_var, out_centers);
    finalize_loss_kernel<<<1, 1>>>(out_loss);
}